// round 5
// baseline (speedup 1.0000x reference)
#include <cuda_runtime.h>
#include <cstdint>
#include <math.h>

#define T_TOK 8192
#define DIM   1024
#define FF    4096
#define NE    8
#define TOPK  2

// ---------------- device scratch (no cudaMalloc allowed) ----------------
__device__ int   g_counts[NE];
__device__ int   g_offsets[NE + 1];
__device__ int   g_cursor[NE];
__device__ int   g_tok_e[T_TOK * TOPK];
__device__ float g_tok_w[T_TOK * TOPK];
__device__ int   g_tok[T_TOK * TOPK];    // token id per flat slot
__device__ float g_wt[T_TOK * TOPK];     // routing weight per flat slot
__device__ float g_H[(size_t)T_TOK * TOPK * FF];   // 268 MB intermediate

// ---------------- helpers ----------------
__device__ __forceinline__ uint32_t f2tf32(float f) {
    uint32_t r;
    asm("cvt.rna.tf32.f32 %0, %1;" : "=r"(r) : "f"(f));
    return r;
}

__device__ __forceinline__ void mma_tf32(float* c, const uint32_t* a, uint32_t b0, uint32_t b1) {
    asm volatile(
        "mma.sync.aligned.m16n8k8.row.col.f32.tf32.tf32.f32 "
        "{%0,%1,%2,%3}, {%4,%5,%6,%7}, {%8,%9}, {%0,%1,%2,%3};\n"
        : "+f"(c[0]), "+f"(c[1]), "+f"(c[2]), "+f"(c[3])
        : "r"(a[0]), "r"(a[1]), "r"(a[2]), "r"(a[3]), "r"(b0), "r"(b1));
}

__device__ __forceinline__ float silu_f(float g) {
    return g / (1.0f + __expf(-g));
}

// ---------------- kernel 0: zero output + counters ----------------
__global__ void moe_zero_kernel(float4* __restrict__ out4) {
    const int n = (T_TOK * DIM) / 4;
    int i = blockIdx.x * blockDim.x + threadIdx.x;
    for (; i < n; i += gridDim.x * blockDim.x)
        out4[i] = make_float4(0.f, 0.f, 0.f, 0.f);
    if (blockIdx.x == 0 && threadIdx.x < NE)
        g_counts[threadIdx.x] = 0;
}

// ---------------- kernel 1: gating (1 warp per token, full fp32) ----------------
__global__ void moe_gate_kernel(const float* __restrict__ x, const float* __restrict__ gw) {
    int warp = (blockIdx.x * blockDim.x + threadIdx.x) >> 5;
    int lane = threadIdx.x & 31;
    if (warp >= T_TOK) return;
    const float* xr = x + (size_t)warp * DIM;

    float acc[NE];
#pragma unroll
    for (int e = 0; e < NE; e++) acc[e] = 0.f;

    for (int d = lane; d < DIM; d += 32) {
        float xv = xr[d];
        const float* g = gw + d * NE;
#pragma unroll
        for (int e = 0; e < NE; e++) acc[e] += xv * g[e];
    }
#pragma unroll
    for (int e = 0; e < NE; e++) {
#pragma unroll
        for (int o = 16; o > 0; o >>= 1)
            acc[e] += __shfl_xor_sync(0xffffffffu, acc[e], o);
    }
    if (lane == 0) {
        int i1 = 0; float v1 = acc[0];
#pragma unroll
        for (int e = 1; e < NE; e++) if (acc[e] > v1) { v1 = acc[e]; i1 = e; }
        int i2 = -1; float v2 = -INFINITY;
#pragma unroll
        for (int e = 0; e < NE; e++) if (e != i1 && acc[e] > v2) { v2 = acc[e]; i2 = e; }
        float e2 = expf(v2 - v1);   // v1 >= v2
        float inv = 1.0f / (1.0f + e2);
        g_tok_e[warp * 2 + 0] = i1;
        g_tok_e[warp * 2 + 1] = i2;
        g_tok_w[warp * 2 + 0] = inv;
        g_tok_w[warp * 2 + 1] = e2 * inv;
        atomicAdd(&g_counts[i1], 1);
        atomicAdd(&g_counts[i2], 1);
    }
}

// ---------------- kernel 2: offsets (tiny) ----------------
__global__ void moe_offset_kernel() {
    int o = 0;
    g_offsets[0] = 0;
#pragma unroll
    for (int e = 0; e < NE; e++) {
        o += g_counts[e];
        g_offsets[e + 1] = o;
        g_cursor[e] = g_offsets[e];
    }
}

// ---------------- kernel 3: scatter tokens into per-expert slots ----------------
__global__ void moe_scatter_kernel() {
    int t = blockIdx.x * blockDim.x + threadIdx.x;
    if (t >= T_TOK) return;
#pragma unroll
    for (int k = 0; k < TOPK; k++) {
        int e = g_tok_e[t * 2 + k];
        int slot = atomicAdd(&g_cursor[e], 1);
        g_tok[slot] = t;
        g_wt[slot] = g_tok_w[t * 2 + k];
    }
}

// ---------------- GEMM config ----------------
// Block tile: 128(M) x 64(N), BK=16, 256 threads, warp grid 4(M) x 2(N), warp tile 32x32.
// smem stride 20 (16 + 4 pad) -> conflict-free fragment reads.
#define STR 20

// ---------------- kernel 4: GEMM1 fused (x@w1, x@w3) + SwiGLU -> g_H ----------------
__global__ __launch_bounds__(256, 1)
void moe_gemm1_kernel(const float* __restrict__ x,
                      const float* __restrict__ w1,
                      const float* __restrict__ w3) {
    int bid = blockIdx.x;
    int mt = bid & 63;              // m fastest: concurrent blocks share B slab in L2
    int nt = (bid >> 6) & 63;       // 64 n-tiles of 64 -> F=4096
    int e  = bid >> 12;

    int row0    = g_offsets[e] + mt * 128;
    int row_end = g_offsets[e + 1];
    if (row0 >= row_end) return;
    int rows = min(128, row_end - row0);

    __shared__ uint32_t sA[2][128 * STR];
    __shared__ uint32_t sB1[2][64 * STR];
    __shared__ uint32_t sB3[2][64 * STR];
    __shared__ int sTok[128];

    int tid = threadIdx.x;
    if (tid < 128) sTok[tid] = (tid < rows) ? g_tok[row0 + tid] : -1;
    __syncthreads();

    const float* w1e = w1 + (size_t)e * DIM * FF;
    const float* w3e = w3 + (size_t)e * DIM * FF;
    const int ncol0 = nt * 64;

    int warp = tid >> 5, lane = tid & 31;
    int wm = warp & 3, wn = warp >> 2;
    int mrow = wm * 32, ncol = wn * 32;
    int grp = lane >> 2, tig = lane & 3;

    float accG[2][4][4], accV[2][4][4];
#pragma unroll
    for (int mi = 0; mi < 2; mi++)
#pragma unroll
        for (int ni = 0; ni < 4; ni++)
#pragma unroll
            for (int q = 0; q < 4; q++) { accG[mi][ni][q] = 0.f; accV[mi][ni][q] = 0.f; }

    // --- stage 0 fill ---
    {
#pragma unroll
        for (int i = 0; i < 2; i++) {
            int idx = tid + i * 256;
            int r = idx >> 2, c4 = idx & 3;
            int tok = sTok[r];
            float4 v = make_float4(0.f, 0.f, 0.f, 0.f);
            if (tok >= 0) v = *(const float4*)(x + (size_t)tok * DIM + c4 * 4);
            uint32_t* d = &sA[0][r * STR + c4 * 4];
            d[0] = f2tf32(v.x); d[1] = f2tf32(v.y); d[2] = f2tf32(v.z); d[3] = f2tf32(v.w);
        }
        int kb = tid >> 4, n4 = tid & 15;
        float4 b1v = *(const float4*)(w1e + (size_t)kb * FF + ncol0 + n4 * 4);
        float4 b3v = *(const float4*)(w3e + (size_t)kb * FF + ncol0 + n4 * 4);
#pragma unroll
        for (int j = 0; j < 4; j++) {
            sB1[0][(n4 * 4 + j) * STR + kb] = f2tf32((&b1v.x)[j]);
            sB3[0][(n4 * 4 + j) * STR + kb] = f2tf32((&b3v.x)[j]);
        }
    }
    __syncthreads();

    const int KT = DIM / 16;   // 64
    for (int kt = 0; kt < KT; kt++) {
        int cur = kt & 1;
        bool nx = (kt + 1 < KT);
        int k0n = (kt + 1) * 16;
        float4 pa0, pa1, pb1, pb3;
        if (nx) {
            {
                int idx = tid;
                int r = idx >> 2, c4 = idx & 3;
                int tok = sTok[r];
                pa0 = (tok >= 0) ? *(const float4*)(x + (size_t)tok * DIM + k0n + c4 * 4)
                                 : make_float4(0.f, 0.f, 0.f, 0.f);
            }
            {
                int idx = tid + 256;
                int r = idx >> 2, c4 = idx & 3;
                int tok = sTok[r];
                pa1 = (tok >= 0) ? *(const float4*)(x + (size_t)tok * DIM + k0n + c4 * 4)
                                 : make_float4(0.f, 0.f, 0.f, 0.f);
            }
            int kb = tid >> 4, n4 = tid & 15;
            pb1 = *(const float4*)(w1e + (size_t)(k0n + kb) * FF + ncol0 + n4 * 4);
            pb3 = *(const float4*)(w3e + (size_t)(k0n + kb) * FF + ncol0 + n4 * 4);
        }
        // --- compute on cur ---
#pragma unroll
        for (int kk = 0; kk < 16; kk += 8) {
            uint32_t a[2][4];
#pragma unroll
            for (int mi = 0; mi < 2; mi++) {
                const uint32_t* Ab = &sA[cur][(mrow + mi * 16 + grp) * STR + kk + tig];
                a[mi][0] = Ab[0];
                a[mi][1] = Ab[8 * STR];
                a[mi][2] = Ab[4];
                a[mi][3] = Ab[8 * STR + 4];
            }
#pragma unroll
            for (int ni = 0; ni < 4; ni++) {
                int cb = (ncol + ni * 8 + grp) * STR + kk + tig;
                uint32_t b10 = sB1[cur][cb], b11 = sB1[cur][cb + 4];
                uint32_t b30 = sB3[cur][cb], b31 = sB3[cur][cb + 4];
#pragma unroll
                for (int mi = 0; mi < 2; mi++) {
                    mma_tf32(accG[mi][ni], a[mi], b10, b11);
                    mma_tf32(accV[mi][ni], a[mi], b30, b31);
                }
            }
        }
        if (nx) {
            int ns = cur ^ 1;
            {
                int idx = tid; int r = idx >> 2, c4 = idx & 3;
                uint32_t* d = &sA[ns][r * STR + c4 * 4];
                d[0] = f2tf32(pa0.x); d[1] = f2tf32(pa0.y); d[2] = f2tf32(pa0.z); d[3] = f2tf32(pa0.w);
            }
            {
                int idx = tid + 256; int r = idx >> 2, c4 = idx & 3;
                uint32_t* d = &sA[ns][r * STR + c4 * 4];
                d[0] = f2tf32(pa1.x); d[1] = f2tf32(pa1.y); d[2] = f2tf32(pa1.z); d[3] = f2tf32(pa1.w);
            }
            int kb = tid >> 4, n4 = tid & 15;
#pragma unroll
            for (int j = 0; j < 4; j++) {
                sB1[ns][(n4 * 4 + j) * STR + kb] = f2tf32((&pb1.x)[j]);
                sB3[ns][(n4 * 4 + j) * STR + kb] = f2tf32((&pb3.x)[j]);
            }
            __syncthreads();
        }
    }

    // --- epilogue: SwiGLU -> g_H ---
#pragma unroll
    for (int mi = 0; mi < 2; mi++) {
#pragma unroll
        for (int ni = 0; ni < 4; ni++) {
            int r = mrow + mi * 16 + grp;
            int c = ncol + ni * 8 + tig * 2;
            size_t gc = (size_t)ncol0 + c;
            const float* g = accG[mi][ni];
            const float* v = accV[mi][ni];
            if (r < rows) {
                float h0 = silu_f(g[0]) * v[0];
                float h1 = silu_f(g[1]) * v[1];
                *(float2*)&g_H[(size_t)(row0 + r) * FF + gc] = make_float2(h0, h1);
            }
            int r2 = r + 8;
            if (r2 < rows) {
                float h2 = silu_f(g[2]) * v[2];
                float h3 = silu_f(g[3]) * v[3];
                *(float2*)&g_H[(size_t)(row0 + r2) * FF + gc] = make_float2(h2, h3);
            }
        }
    }
}

// ---------------- kernel 5: GEMM2 (H @ w2) scaled scatter-add ----------------
__global__ __launch_bounds__(256, 1)
void moe_gemm2_kernel(const float* __restrict__ w2, float* __restrict__ out) {
    int bid = blockIdx.x;
    int nt = bid & 15;              // n fastest: concurrent blocks share A/H slab in L2
    int mt = (bid >> 4) & 63;
    int e  = bid >> 10;

    int row0    = g_offsets[e] + mt * 128;
    int row_end = g_offsets[e + 1];
    if (row0 >= row_end) return;
    int rows = min(128, row_end - row0);

    __shared__ uint32_t sA[2][128 * STR];
    __shared__ uint32_t sB[2][64 * STR];
    __shared__ int   sTok[128];
    __shared__ float sWt[128];

    int tid = threadIdx.x;
    if (tid < 128) {
        bool ok = tid < rows;
        sTok[tid] = ok ? g_tok[row0 + tid] : -1;
        sWt[tid]  = ok ? g_wt[row0 + tid] : 0.f;
    }
    __syncthreads();

    const float* w2e = w2 + (size_t)e * FF * DIM;
    const int ncol0 = nt * 64;

    int warp = tid >> 5, lane = tid & 31;
    int wm = warp & 3, wn = warp >> 2;
    int mrow = wm * 32, ncol = wn * 32;
    int grp = lane >> 2, tig = lane & 3;

    float accC[2][4][4];
#pragma unroll
    for (int mi = 0; mi < 2; mi++)
#pragma unroll
        for (int ni = 0; ni < 4; ni++)
#pragma unroll
            for (int q = 0; q < 4; q++) accC[mi][ni][q] = 0.f;

    // --- stage 0 fill ---
    {
#pragma unroll
        for (int i = 0; i < 2; i++) {
            int idx = tid + i * 256;
            int r = idx >> 2, c4 = idx & 3;
            float4 v = make_float4(0.f, 0.f, 0.f, 0.f);
            if (r < rows) v = *(const float4*)(&g_H[(size_t)(row0 + r) * FF + c4 * 4]);
            uint32_t* d = &sA[0][r * STR + c4 * 4];
            d[0] = f2tf32(v.x); d[1] = f2tf32(v.y); d[2] = f2tf32(v.z); d[3] = f2tf32(v.w);
        }
        int kb = tid >> 4, n4 = tid & 15;
        float4 bv = *(const float4*)(w2e + (size_t)kb * DIM + ncol0 + n4 * 4);
#pragma unroll
        for (int j = 0; j < 4; j++)
            sB[0][(n4 * 4 + j) * STR + kb] = f2tf32((&bv.x)[j]);
    }
    __syncthreads();

    const int KT = FF / 16;   // 256
    for (int kt = 0; kt < KT; kt++) {
        int cur = kt & 1;
        bool nx = (kt + 1 < KT);
        int k0n = (kt + 1) * 16;
        float4 pa0, pa1, pb;
        if (nx) {
            {
                int idx = tid; int r = idx >> 2, c4 = idx & 3;
                pa0 = (r < rows) ? *(const float4*)(&g_H[(size_t)(row0 + r) * FF + k0n + c4 * 4])
                                 : make_float4(0.f, 0.f, 0.f, 0.f);
            }
            {
                int idx = tid + 256; int r = idx >> 2, c4 = idx & 3;
                pa1 = (r < rows) ? *(const float4*)(&g_H[(size_t)(row0 + r) * FF + k0n + c4 * 4])
                                 : make_float4(0.f, 0.f, 0.f, 0.f);
            }
            int kb = tid >> 4, n4 = tid & 15;
            pb = *(const float4*)(w2e + (size_t)(k0n + kb) * DIM + ncol0 + n4 * 4);
        }
#pragma unroll
        for (int kk = 0; kk < 16; kk += 8) {
            uint32_t a[2][4];
#pragma unroll
            for (int mi = 0; mi < 2; mi++) {
                const uint32_t* Ab = &sA[cur][(mrow + mi * 16 + grp) * STR + kk + tig];
                a[mi][0] = Ab[0];
                a[mi][1] = Ab[8 * STR];
                a[mi][2] = Ab[4];
                a[mi][3] = Ab[8 * STR + 4];
            }
#pragma unroll
            for (int ni = 0; ni < 4; ni++) {
                int cb = (ncol + ni * 8 + grp) * STR + kk + tig;
                uint32_t b0 = sB[cur][cb], b1 = sB[cur][cb + 4];
#pragma unroll
                for (int mi = 0; mi < 2; mi++)
                    mma_tf32(accC[mi][ni], a[mi], b0, b1);
            }
        }
        if (nx) {
            int ns = cur ^ 1;
            {
                int idx = tid; int r = idx >> 2, c4 = idx & 3;
                uint32_t* d = &sA[ns][r * STR + c4 * 4];
                d[0] = f2tf32(pa0.x); d[1] = f2tf32(pa0.y); d[2] = f2tf32(pa0.z); d[3] = f2tf32(pa0.w);
            }
            {
                int idx = tid + 256; int r = idx >> 2, c4 = idx & 3;
                uint32_t* d = &sA[ns][r * STR + c4 * 4];
                d[0] = f2tf32(pa1.x); d[1] = f2tf32(pa1.y); d[2] = f2tf32(pa1.z); d[3] = f2tf32(pa1.w);
            }
            int kb = tid >> 4, n4 = tid & 15;
#pragma unroll
            for (int j = 0; j < 4; j++)
                sB[ns][(n4 * 4 + j) * STR + kb] = f2tf32((&pb.x)[j]);
            __syncthreads();
        }
    }

    // --- epilogue: weight * acc, atomic scatter-add into out ---
#pragma unroll
    for (int mi = 0; mi < 2; mi++) {
#pragma unroll
        for (int ni = 0; ni < 4; ni++) {
            int r = mrow + mi * 16 + grp;
            int c = ncol + ni * 8 + tig * 2;
            size_t gc = (size_t)ncol0 + c;
            const float* a = accC[mi][ni];
            if (r < rows) {
                int tok = sTok[r]; float wq = sWt[r];
                float* p = &out[(size_t)tok * DIM + gc];
                atomicAdd(p + 0, a[0] * wq);
                atomicAdd(p + 1, a[1] * wq);
            }
            int r2 = r + 8;
            if (r2 < rows) {
                int tok = sTok[r2]; float wq = sWt[r2];
                float* p = &out[(size_t)tok * DIM + gc];
                atomicAdd(p + 0, a[2] * wq);
                atomicAdd(p + 1, a[3] * wq);
            }
        }
    }
}

// ---------------- launch ----------------
extern "C" void kernel_launch(void* const* d_in, const int* in_sizes, int n_in,
                              void* d_out, int out_size) {
    (void)in_sizes; (void)n_in; (void)out_size;
    const float* x  = (const float*)d_in[0];
    const float* gw = (const float*)d_in[1];
    const float* w1 = (const float*)d_in[2];
    const float* w3 = (const float*)d_in[3];
    const float* w2 = (const float*)d_in[4];
    float* out = (float*)d_out;

    moe_zero_kernel<<<2048, 256>>>((float4*)out);
    moe_gate_kernel<<<T_TOK / 8, 256>>>(x, gw);
    moe_offset_kernel<<<1, 1>>>();
    moe_scatter_kernel<<<T_TOK / 256, 256>>>();
    // GEMM1: grid = E(8) * n_tiles(64) * m_tiles_max(64), m fastest
    moe_gemm1_kernel<<<8 * 64 * 64, 256>>>(x, w1, w3);
    // GEMM2: grid = E(8) * m_tiles_max(64) * n_tiles(16), n fastest
    moe_gemm2_kernel<<<8 * 64 * 16, 256>>>(w2, out);
}

// round 7
// speedup vs baseline: 2.8518x; 2.8518x over previous
#include <cuda_runtime.h>
#include <cstdint>
#include <math.h>

#define T_TOK 8192
#define DIM   1024
#define FF    4096
#define NE    8
#define SLOTS (T_TOK * 2)

// ---------------- device scratch ----------------
__device__ int   g_counts[NE];
__device__ int   g_offsets[NE + 1];
__device__ int   g_cursor[NE];
__device__ int   g_tok_e[SLOTS];
__device__ float g_tok_w[SLOTS];
__device__ int   g_tok[SLOTS];                  // slot -> token
__device__ int   g_slot[SLOTS];                 // token*2+k -> slot
__device__ float g_H[(size_t)SLOTS * FF];       // 256MB SwiGLU intermediate (tf32-rounded)
__device__ float g_R[(size_t)SLOTS * DIM];      // 64MB down-proj per slot (fp32)
__device__ float g_xr[(size_t)T_TOK * DIM];     // tf32-rounded x
__device__ float g_w1r[(size_t)NE * DIM * FF];  // tf32-rounded weights
__device__ float g_w3r[(size_t)NE * DIM * FF];
__device__ float g_w2r[(size_t)NE * FF * DIM];

// ---------------- helpers ----------------
__device__ __forceinline__ uint32_t smem_u32(const void* p) {
    uint32_t a;
    asm("{ .reg .u64 t; cvta.to.shared.u64 t, %1; cvt.u32.u64 %0, t; }" : "=r"(a) : "l"(p));
    return a;
}
__device__ __forceinline__ uint32_t f2tf32(float f) {
    uint32_t r; asm("cvt.rna.tf32.f32 %0, %1;" : "=r"(r) : "f"(f)); return r;
}
#define CP_ASYNC16(dst, src) \
    asm volatile("cp.async.cg.shared.global [%0], [%1], 16;" :: "r"(dst), "l"(src) : "memory")
#define CP_COMMIT() asm volatile("cp.async.commit_group;" ::: "memory")
#define CP_WAIT(n)  asm volatile("cp.async.wait_group %0;" :: "n"(n) : "memory")

__device__ __forceinline__ void mma_tf32(float* c, const uint32_t* a, uint32_t b0, uint32_t b1) {
    asm volatile(
        "mma.sync.aligned.m16n8k8.row.col.f32.tf32.tf32.f32 "
        "{%0,%1,%2,%3}, {%4,%5,%6,%7}, {%8,%9}, {%0,%1,%2,%3};\n"
        : "+f"(c[0]), "+f"(c[1]), "+f"(c[2]), "+f"(c[3])
        : "r"(a[0]), "r"(a[1]), "r"(a[2]), "r"(a[3]), "r"(b0), "r"(b1));
}
__device__ __forceinline__ float silu_f(float g) { return g / (1.0f + __expf(-g)); }

// ---------------- kernel: round fp32 -> tf32-rounded fp32 ----------------
__global__ void moe_round_kernel(const float4* __restrict__ src, float4* __restrict__ dst, int n4) {
    int i = blockIdx.x * blockDim.x + threadIdx.x;
    if (i >= n4) return;
    float4 v = src[i];
    float4 o;
    o.x = __uint_as_float(f2tf32(v.x));
    o.y = __uint_as_float(f2tf32(v.y));
    o.z = __uint_as_float(f2tf32(v.z));
    o.w = __uint_as_float(f2tf32(v.w));
    dst[i] = o;
}

// ---------------- small kernels ----------------
__global__ void moe_init_kernel() {
    if (threadIdx.x < NE) g_counts[threadIdx.x] = 0;
}

__global__ void moe_gate_kernel(const float* __restrict__ x, const float* __restrict__ gw) {
    int warp = (blockIdx.x * blockDim.x + threadIdx.x) >> 5;
    int lane = threadIdx.x & 31;
    if (warp >= T_TOK) return;
    const float* xr = x + (size_t)warp * DIM;
    float acc[NE];
#pragma unroll
    for (int e = 0; e < NE; e++) acc[e] = 0.f;
    for (int d = lane; d < DIM; d += 32) {
        float xv = xr[d];
        const float* g = gw + d * NE;
#pragma unroll
        for (int e = 0; e < NE; e++) acc[e] += xv * g[e];
    }
#pragma unroll
    for (int e = 0; e < NE; e++)
#pragma unroll
        for (int o = 16; o > 0; o >>= 1) acc[e] += __shfl_xor_sync(0xffffffffu, acc[e], o);
    if (lane == 0) {
        int i1 = 0; float v1 = acc[0];
#pragma unroll
        for (int e = 1; e < NE; e++) if (acc[e] > v1) { v1 = acc[e]; i1 = e; }
        int i2 = -1; float v2 = -INFINITY;
#pragma unroll
        for (int e = 0; e < NE; e++) if (e != i1 && acc[e] > v2) { v2 = acc[e]; i2 = e; }
        float e2 = expf(v2 - v1);
        float inv = 1.0f / (1.0f + e2);
        g_tok_e[warp * 2 + 0] = i1;
        g_tok_e[warp * 2 + 1] = i2;
        g_tok_w[warp * 2 + 0] = inv;
        g_tok_w[warp * 2 + 1] = e2 * inv;
        atomicAdd(&g_counts[i1], 1);
        atomicAdd(&g_counts[i2], 1);
    }
}

__global__ void moe_offset_kernel() {
    int o = 0;
    g_offsets[0] = 0;
#pragma unroll
    for (int e = 0; e < NE; e++) {
        o += g_counts[e];
        g_offsets[e + 1] = o;
        g_cursor[e] = g_offsets[e];
    }
}

__global__ void moe_scatter_kernel() {
    int t = blockIdx.x * blockDim.x + threadIdx.x;
    if (t >= T_TOK) return;
#pragma unroll
    for (int k = 0; k < 2; k++) {
        int e = g_tok_e[t * 2 + k];
        int slot = atomicAdd(&g_cursor[e], 1);
        g_tok[slot] = t;
        g_slot[t * 2 + k] = slot;
    }
}

// ---------------- GEMM config ----------------
// Block 128M x 64N, BK=32, 256 threads, warps 4m x 2n, warp tile 32x32 (per mat).
// A smem: [128 rows][36 words] (32 k + 4 pad). Row = 144 B.
// B smem: [32 k-rows][72 words] (64 n + 8 pad). Row = 288 B.
#define SA_W   36
#define SB_W   72
#define A_BYTES 18432          // 128*36*4
#define B_BYTES 9216           // 32*72*4
#define STG1   36864           // A + B1 + B3
#define STG2   27648           // A + B

// ---------------- GEMM1: x@w1, x@w3 -> SwiGLU -> g_H ----------------
__device__ __forceinline__ void fill1(uint32_t sb, int kc, int ncol0,
                                      const float* __restrict__ w1e,
                                      const float* __restrict__ w3e,
                                      const int* sTok, int tid) {
    int k0 = kc * 32;
#pragma unroll
    for (int i = 0; i < 4; i++) {
        int c = tid + i * 256;
        int r = c >> 3, c4 = c & 7;
        const float* src = g_xr + (size_t)sTok[r] * DIM + k0 + c4 * 4;
        CP_ASYNC16(sb + r * 144 + c4 * 16, src);
    }
    const float* w = (tid < 128) ? w1e : w3e;
    uint32_t boff = sb + ((tid < 128) ? A_BYTES : (A_BYTES + B_BYTES));
    int t = tid & 127;
#pragma unroll
    for (int i = 0; i < 4; i++) {
        int c = t + i * 128;
        int kr = c >> 4, n4 = c & 15;
        const float* src = w + (size_t)(k0 + kr) * FF + ncol0 + n4 * 4;
        CP_ASYNC16(boff + kr * 288 + n4 * 16, src);
    }
}

__global__ __launch_bounds__(256, 2)
void moe_gemm1(const float* __restrict__ w1r, const float* __restrict__ w3r) {
    int bid = blockIdx.x;
    int mt = bid & 63, nt = (bid >> 6) & 63, e = bid >> 12;
    int row0 = g_offsets[e] + mt * 128;
    int row_end = g_offsets[e + 1];
    if (row0 >= row_end) return;
    int rows = min(128, row_end - row0);

    extern __shared__ char dsm[];
    __shared__ int sTok[128];

    int tid = threadIdx.x;
    if (tid < 128) sTok[tid] = g_tok[row0 + ((tid < rows) ? tid : 0)];
    __syncthreads();

    uint32_t smem0 = smem_u32(dsm);
    const float* w1e = w1r + (size_t)e * DIM * FF;
    const float* w3e = w3r + (size_t)e * DIM * FF;
    int ncol0 = nt * 64;

    int warp = tid >> 5, lane = tid & 31;
    int wm = warp & 3, wn = warp >> 2;
    int mrow = wm * 32, ncol = wn * 32;
    int grp = lane >> 2, tig = lane & 3;

    float accG[2][4][4], accV[2][4][4];
#pragma unroll
    for (int mi = 0; mi < 2; mi++)
#pragma unroll
        for (int ni = 0; ni < 4; ni++)
#pragma unroll
            for (int q = 0; q < 4; q++) { accG[mi][ni][q] = 0.f; accV[mi][ni][q] = 0.f; }

    fill1(smem0 + 0 * STG1, 0, ncol0, w1e, w3e, sTok, tid); CP_COMMIT();
    fill1(smem0 + 1 * STG1, 1, ncol0, w1e, w3e, sTok, tid); CP_COMMIT();

    const int KT = DIM / 32;   // 32
    for (int kt = 0; kt < KT; kt++) {
        CP_WAIT(1);
        __syncthreads();
        if (kt + 2 < KT)
            fill1(smem0 + ((kt + 2) % 3) * STG1, kt + 2, ncol0, w1e, w3e, sTok, tid);
        CP_COMMIT();

        const uint32_t* sA  = (const uint32_t*)(dsm + (kt % 3) * STG1);
        const uint32_t* sB1 = sA + A_BYTES / 4;
        const uint32_t* sB3 = sA + (A_BYTES + B_BYTES) / 4;
#pragma unroll
        for (int kk = 0; kk < 32; kk += 8) {
            uint32_t a[2][4];
#pragma unroll
            for (int mi = 0; mi < 2; mi++) {
                int base = (mrow + mi * 16 + grp) * SA_W + kk + tig;
                a[mi][0] = sA[base];
                a[mi][1] = sA[base + 8 * SA_W];
                a[mi][2] = sA[base + 4];
                a[mi][3] = sA[base + 8 * SA_W + 4];
            }
#pragma unroll
            for (int ni = 0; ni < 4; ni++) {
                int kb = (kk + tig) * SB_W + ncol + ni * 8 + grp;
                uint32_t b10 = sB1[kb], b11 = sB1[kb + 4 * SB_W];
                uint32_t b30 = sB3[kb], b31 = sB3[kb + 4 * SB_W];
#pragma unroll
                for (int mi = 0; mi < 2; mi++) {
                    mma_tf32(accG[mi][ni], a[mi], b10, b11);
                    mma_tf32(accV[mi][ni], a[mi], b30, b31);
                }
            }
        }
    }

    // epilogue: SwiGLU, round to tf32, store to g_H
#pragma unroll
    for (int mi = 0; mi < 2; mi++) {
#pragma unroll
        for (int ni = 0; ni < 4; ni++) {
            int r = mrow + mi * 16 + grp;
            int c = ncol + ni * 8 + tig * 2;
            size_t gc = (size_t)ncol0 + c;
            const float* g = accG[mi][ni];
            const float* v = accV[mi][ni];
            if (r < rows) {
                float h0 = silu_f(g[0]) * v[0];
                float h1 = silu_f(g[1]) * v[1];
                *(float2*)&g_H[(size_t)(row0 + r) * FF + gc] =
                    make_float2(__uint_as_float(f2tf32(h0)), __uint_as_float(f2tf32(h1)));
            }
            int r2 = r + 8;
            if (r2 < rows) {
                float h2 = silu_f(g[2]) * v[2];
                float h3 = silu_f(g[3]) * v[3];
                *(float2*)&g_H[(size_t)(row0 + r2) * FF + gc] =
                    make_float2(__uint_as_float(f2tf32(h2)), __uint_as_float(f2tf32(h3)));
            }
        }
    }
}

// ---------------- GEMM2: g_H @ w2 -> g_R ----------------
__device__ __forceinline__ void fill2(uint32_t sb, int kc, int ncol0,
                                      const float* __restrict__ w2e,
                                      int row0, int rows, int tid) {
    int k0 = kc * 32;
#pragma unroll
    for (int i = 0; i < 4; i++) {
        int c = tid + i * 256;
        int r = c >> 3, c4 = c & 7;
        int rsrc = row0 + ((r < rows) ? r : 0);
        const float* src = g_H + (size_t)rsrc * FF + k0 + c4 * 4;
        CP_ASYNC16(sb + r * 144 + c4 * 16, src);
    }
#pragma unroll
    for (int i = 0; i < 2; i++) {
        int c = tid + i * 256;
        int kr = c >> 4, n4 = c & 15;
        const float* src = w2e + (size_t)(k0 + kr) * DIM + ncol0 + n4 * 4;
        CP_ASYNC16(sb + A_BYTES + kr * 288 + n4 * 16, src);
    }
}

__global__ __launch_bounds__(256, 2)
void moe_gemm2(const float* __restrict__ w2r) {
    int bid = blockIdx.x;
    int nt = bid & 15, mt = (bid >> 4) & 63, e = bid >> 10;
    int row0 = g_offsets[e] + mt * 128;
    int row_end = g_offsets[e + 1];
    if (row0 >= row_end) return;
    int rows = min(128, row_end - row0);

    extern __shared__ char dsm[];
    int tid = threadIdx.x;
    uint32_t smem0 = smem_u32(dsm);
    const float* w2e = w2r + (size_t)e * FF * DIM;
    int ncol0 = nt * 64;

    int warp = tid >> 5, lane = tid & 31;
    int wm = warp & 3, wn = warp >> 2;
    int mrow = wm * 32, ncol = wn * 32;
    int grp = lane >> 2, tig = lane & 3;

    float accC[2][4][4];
#pragma unroll
    for (int mi = 0; mi < 2; mi++)
#pragma unroll
        for (int ni = 0; ni < 4; ni++)
#pragma unroll
            for (int q = 0; q < 4; q++) accC[mi][ni][q] = 0.f;

    fill2(smem0 + 0 * STG2, 0, ncol0, w2e, row0, rows, tid); CP_COMMIT();
    fill2(smem0 + 1 * STG2, 1, ncol0, w2e, row0, rows, tid); CP_COMMIT();
    fill2(smem0 + 2 * STG2, 2, ncol0, w2e, row0, rows, tid); CP_COMMIT();

    const int KT = FF / 32;   // 128
    for (int kt = 0; kt < KT; kt++) {
        CP_WAIT(2);
        __syncthreads();
        if (kt + 3 < KT)
            fill2(smem0 + ((kt + 3) & 3) * STG2, kt + 3, ncol0, w2e, row0, rows, tid);
        CP_COMMIT();

        const uint32_t* sA = (const uint32_t*)(dsm + (kt & 3) * STG2);
        const uint32_t* sB = sA + A_BYTES / 4;
#pragma unroll
        for (int kk = 0; kk < 32; kk += 8) {
            uint32_t a[2][4];
#pragma unroll
            for (int mi = 0; mi < 2; mi++) {
                int base = (mrow + mi * 16 + grp) * SA_W + kk + tig;
                a[mi][0] = sA[base];
                a[mi][1] = sA[base + 8 * SA_W];
                a[mi][2] = sA[base + 4];
                a[mi][3] = sA[base + 8 * SA_W + 4];
            }
#pragma unroll
            for (int ni = 0; ni < 4; ni++) {
                int kb = (kk + tig) * SB_W + ncol + ni * 8 + grp;
                uint32_t b0 = sB[kb], b1 = sB[kb + 4 * SB_W];
#pragma unroll
                for (int mi = 0; mi < 2; mi++)
                    mma_tf32(accC[mi][ni], a[mi], b0, b1);
            }
        }
    }

    // epilogue: raw fp32 per-slot rows
#pragma unroll
    for (int mi = 0; mi < 2; mi++) {
#pragma unroll
        for (int ni = 0; ni < 4; ni++) {
            int r = mrow + mi * 16 + grp;
            int c = ncol + ni * 8 + tig * 2;
            size_t gc = (size_t)ncol0 + c;
            const float* a = accC[mi][ni];
            if (r < rows)
                *(float2*)&g_R[(size_t)(row0 + r) * DIM + gc] = make_float2(a[0], a[1]);
            int r2 = r + 8;
            if (r2 < rows)
                *(float2*)&g_R[(size_t)(row0 + r2) * DIM + gc] = make_float2(a[2], a[3]);
        }
    }
}

// ---------------- combine: out[t] = w0*R[s0] + w1*R[s1] ----------------
__global__ void moe_combine_kernel(float4* __restrict__ out4) {
    const int n = T_TOK * (DIM / 4);
    int i = blockIdx.x * blockDim.x + threadIdx.x;
    if (i >= n) return;
    int t = i >> 8;            // DIM/4 = 256
    int c = i & 255;
    int s0 = g_slot[t * 2 + 0], s1 = g_slot[t * 2 + 1];
    float w0 = g_tok_w[t * 2 + 0], w1 = g_tok_w[t * 2 + 1];
    const float4* R4 = (const float4*)g_R;
    float4 a = R4[(size_t)s0 * 256 + c];
    float4 b = R4[(size_t)s1 * 256 + c];
    float4 o;
    o.x = w0 * a.x + w1 * b.x;
    o.y = w0 * a.y + w1 * b.y;
    o.z = w0 * a.z + w1 * b.z;
    o.w = w0 * a.w + w1 * b.w;
    out4[i] = o;
}

// ---------------- launch ----------------
extern "C" void kernel_launch(void* const* d_in, const int* in_sizes, int n_in,
                              void* d_out, int out_size) {
    (void)in_sizes; (void)n_in; (void)out_size;
    const float* x  = (const float*)d_in[0];
    const float* gw = (const float*)d_in[1];
    const float* w1 = (const float*)d_in[2];
    const float* w3 = (const float*)d_in[3];
    const float* w2 = (const float*)d_in[4];
    float* out = (float*)d_out;

    static float* xr_p  = nullptr;
    float* d_xr;  cudaGetSymbolAddress((void**)&d_xr,  g_xr);
    float* d_w1r; cudaGetSymbolAddress((void**)&d_w1r, g_w1r);
    float* d_w3r; cudaGetSymbolAddress((void**)&d_w3r, g_w3r);
    float* d_w2r; cudaGetSymbolAddress((void**)&d_w2r, g_w2r);
    (void)xr_p;

    const int DYN1 = 3 * STG1;   // 110592
    const int DYN2 = 4 * STG2;   // 110592
    cudaFuncSetAttribute(moe_gemm1, cudaFuncAttributeMaxDynamicSharedMemorySize, DYN1);
    cudaFuncSetAttribute(moe_gemm2, cudaFuncAttributeMaxDynamicSharedMemorySize, DYN2);

    moe_init_kernel<<<1, 32>>>();

    // pre-round inputs/weights to tf32 (bit-exact with cvt-in-fill path)
    int nx = T_TOK * DIM / 4, nw = NE * DIM * FF / 4;
    moe_round_kernel<<<(nx + 255) / 256, 256>>>((const float4*)x,  (float4*)d_xr,  nx);
    moe_round_kernel<<<(nw + 255) / 256, 256>>>((const float4*)w1, (float4*)d_w1r, nw);
    moe_round_kernel<<<(nw + 255) / 256, 256>>>((const float4*)w3, (float4*)d_w3r, nw);
    moe_round_kernel<<<(nw + 255) / 256, 256>>>((const float4*)w2, (float4*)d_w2r, nw);

    moe_gate_kernel<<<T_TOK / 8, 256>>>(x, gw);
    moe_offset_kernel<<<1, 1>>>();
    moe_scatter_kernel<<<T_TOK / 256, 256>>>();

    // GEMM1: e(8) x nt(64) x mt(64), mt fastest (concurrent blocks share B slab)
    moe_gemm1<<<8 * 64 * 64, 256, DYN1>>>(d_w1r, d_w3r);
    // GEMM2: e(8) x mt(64) x nt(16), nt fastest (concurrent blocks share H slab)
    moe_gemm2<<<8 * 64 * 16, 256, DYN2>>>(d_w2r);

    moe_combine_kernel<<<(T_TOK * DIM / 4 + 255) / 256, 256>>>((float4*)out);
}

// round 8
// speedup vs baseline: 2.9556x; 1.0364x over previous
#include <cuda_runtime.h>
#include <cstdint>
#include <math.h>

#define T_TOK 8192
#define DIM   1024
#define FF    4096
#define NE    8
#define SLOTS (T_TOK * 2)

// ---------------- device scratch ----------------
__device__ int   g_offsets[NE + 1];
__device__ int   g_cursor[NE];
__device__ int   g_tok_e[SLOTS];
__device__ float g_tok_w[SLOTS];
__device__ int   g_tok[SLOTS];                  // slot -> token
__device__ int   g_slot[SLOTS];                 // token*2+k -> slot
__device__ float g_H[(size_t)SLOTS * FF];       // SwiGLU intermediate (tf32-rounded)
__device__ float g_R[(size_t)SLOTS * DIM];      // down-proj per slot (fp32)
__device__ float g_xr[(size_t)T_TOK * DIM];     // tf32-rounded x
__device__ float g_w1r[(size_t)NE * DIM * FF];
__device__ float g_w3r[(size_t)NE * DIM * FF];
__device__ float g_w2r[(size_t)NE * FF * DIM];

// ---------------- helpers ----------------
__device__ __forceinline__ uint32_t smem_u32(const void* p) {
    uint32_t a;
    asm("{ .reg .u64 t; cvta.to.shared.u64 t, %1; cvt.u32.u64 %0, t; }" : "=r"(a) : "l"(p));
    return a;
}
__device__ __forceinline__ uint32_t f2tf32(float f) {
    uint32_t r; asm("cvt.rna.tf32.f32 %0, %1;" : "=r"(r) : "f"(f)); return r;
}
#define CP_ASYNC16(dst, src) \
    asm volatile("cp.async.cg.shared.global [%0], [%1], 16;" :: "r"(dst), "l"(src) : "memory")
#define CP_COMMIT() asm volatile("cp.async.commit_group;" ::: "memory")
#define CP_WAIT(n)  asm volatile("cp.async.wait_group %0;" :: "n"(n) : "memory")

__device__ __forceinline__ void ldsm_x4(uint32_t* r, uint32_t addr) {
    asm volatile("ldmatrix.sync.aligned.m8n8.x4.shared.b16 {%0,%1,%2,%3}, [%4];"
        : "=r"(r[0]), "=r"(r[1]), "=r"(r[2]), "=r"(r[3]) : "r"(addr));
}
__device__ __forceinline__ void mma_tf32(float* c, const uint32_t* a, uint32_t b0, uint32_t b1) {
    asm volatile(
        "mma.sync.aligned.m16n8k8.row.col.f32.tf32.tf32.f32 "
        "{%0,%1,%2,%3}, {%4,%5,%6,%7}, {%8,%9}, {%0,%1,%2,%3};\n"
        : "+f"(c[0]), "+f"(c[1]), "+f"(c[2]), "+f"(c[3])
        : "r"(a[0]), "r"(a[1]), "r"(a[2]), "r"(a[3]), "r"(b0), "r"(b1));
}
__device__ __forceinline__ float silu_f(float g) { return g / (1.0f + __expf(-g)); }

// ---------------- launch #1: round all 3 weight tensors (gridDim.y selects) ----------------
__global__ void moe_round_w(const float4* __restrict__ w1, float4* __restrict__ d1,
                            const float4* __restrict__ w3, float4* __restrict__ d3,
                            const float4* __restrict__ w2, float4* __restrict__ d2, int n4) {
    const float4* s; float4* d;
    if (blockIdx.y == 0)      { s = w1; d = d1; }
    else if (blockIdx.y == 1) { s = w3; d = d3; }
    else                      { s = w2; d = d2; }
    int i = blockIdx.x * blockDim.x + threadIdx.x;
    if (i >= n4) return;
    float4 v = s[i], o;
    o.x = __uint_as_float(f2tf32(v.x));
    o.y = __uint_as_float(f2tf32(v.y));
    o.z = __uint_as_float(f2tf32(v.z));
    o.w = __uint_as_float(f2tf32(v.w));
    d[i] = o;
}

// ---------------- launch #2: round x ----------------
__global__ void moe_round_x(const float4* __restrict__ src, float4* __restrict__ dst, int n4) {
    int i = blockIdx.x * blockDim.x + threadIdx.x;
    if (i >= n4) return;
    float4 v = src[i], o;
    o.x = __uint_as_float(f2tf32(v.x));
    o.y = __uint_as_float(f2tf32(v.y));
    o.z = __uint_as_float(f2tf32(v.z));
    o.w = __uint_as_float(f2tf32(v.w));
    dst[i] = o;
}

// ---------------- launch #3: gating (no atomics) ----------------
__global__ void moe_gate_kernel(const float* __restrict__ x, const float* __restrict__ gw) {
    int warp = (blockIdx.x * blockDim.x + threadIdx.x) >> 5;
    int lane = threadIdx.x & 31;
    if (warp >= T_TOK) return;
    const float* xr = x + (size_t)warp * DIM;
    float acc[NE];
#pragma unroll
    for (int e = 0; e < NE; e++) acc[e] = 0.f;
    for (int d = lane; d < DIM; d += 32) {
        float xv = xr[d];
        const float* g = gw + d * NE;
#pragma unroll
        for (int e = 0; e < NE; e++) acc[e] += xv * g[e];
    }
#pragma unroll
    for (int e = 0; e < NE; e++)
#pragma unroll
        for (int o = 16; o > 0; o >>= 1) acc[e] += __shfl_xor_sync(0xffffffffu, acc[e], o);
    if (lane == 0) {
        int i1 = 0; float v1 = acc[0];
#pragma unroll
        for (int e = 1; e < NE; e++) if (acc[e] > v1) { v1 = acc[e]; i1 = e; }
        int i2 = -1; float v2 = -INFINITY;
#pragma unroll
        for (int e = 0; e < NE; e++) if (e != i1 && acc[e] > v2) { v2 = acc[e]; i2 = e; }
        float e2 = expf(v2 - v1);
        float inv = 1.0f / (1.0f + e2);
        g_tok_e[warp * 2 + 0] = i1;
        g_tok_e[warp * 2 + 1] = i2;
        g_tok_w[warp * 2 + 0] = inv;
        g_tok_w[warp * 2 + 1] = e2 * inv;
    }
}

// ---------------- launch #4: count + offsets via scan (one block) ----------------
__global__ void moe_offset_kernel() {
    __shared__ int sc[NE];
    int tid = threadIdx.x;
    if (tid < NE) sc[tid] = 0;
    __syncthreads();
    int loc[NE];
#pragma unroll
    for (int e = 0; e < NE; e++) loc[e] = 0;
    for (int i = tid; i < SLOTS; i += blockDim.x) loc[g_tok_e[i]]++;
#pragma unroll
    for (int e = 0; e < NE; e++) if (loc[e]) atomicAdd(&sc[e], loc[e]);
    __syncthreads();
    if (tid == 0) {
        int o = 0;
        g_offsets[0] = 0;
#pragma unroll
        for (int e = 0; e < NE; e++) {
            o += sc[e];
            g_offsets[e + 1] = o;
            g_cursor[e] = g_offsets[e];
        }
    }
}

// ---------------- launch #5: scatter ----------------
__global__ void moe_scatter_kernel() {
    int t = blockIdx.x * blockDim.x + threadIdx.x;
    if (t >= T_TOK) return;
#pragma unroll
    for (int k = 0; k < 2; k++) {
        int e = g_tok_e[t * 2 + k];
        int slot = atomicAdd(&g_cursor[e], 1);
        g_tok[slot] = t;
        g_slot[t * 2 + k] = slot;
    }
}

// ---------------- GEMM config ----------------
// BK=32. A smem row: 32k + 4 pad = 36 words (144B). B smem row: 128n + 8 pad = 136 words (544B).
#define SA_W    36
#define SB_W    136
#define A_BYTES 18432            // 128*144
#define B_BYTES 17408            // 32*544
#define STG1    (A_BYTES + 2 * B_BYTES)   // 53248
#define STG2    (A_BYTES + B_BYTES)       // 35840

// ---------------- launch #6: GEMM1 x@w1,x@w3 -> SwiGLU -> g_H ----------------
// 512 threads, tile 128M x 128N (per mat), warps 4m x 4n, warp tile 32x32/mat.
__device__ __forceinline__ void fill1(uint32_t sb, int kc, int ncol0,
                                      const float* __restrict__ w1e,
                                      const float* __restrict__ w3e,
                                      const int* sTok, int tid) {
    int k0 = kc * 32;
#pragma unroll
    for (int i = 0; i < 2; i++) {
        int c = tid + i * 512;
        int r = c >> 3, c4 = c & 7;
        const float* src = g_xr + (size_t)sTok[r] * DIM + k0 + c4 * 4;
        CP_ASYNC16(sb + r * 144 + c4 * 16, src);
    }
    const float* w = (tid < 256) ? w1e : w3e;
    uint32_t boff = sb + ((tid < 256) ? A_BYTES : (A_BYTES + B_BYTES));
    int t = tid & 255;
#pragma unroll
    for (int i = 0; i < 4; i++) {
        int c = t + i * 256;
        int kr = c >> 5, n4 = c & 31;
        const float* src = w + (size_t)(k0 + kr) * FF + ncol0 + n4 * 4;
        CP_ASYNC16(boff + kr * 544 + n4 * 16, src);
    }
}

__global__ __launch_bounds__(512, 1)
void moe_gemm1(const float* __restrict__ w1r, const float* __restrict__ w3r) {
    int bid = blockIdx.x;
    int mt = bid & 63, nt = (bid >> 6) & 31, e = bid >> 11;
    int row0 = g_offsets[e] + mt * 128;
    int row_end = g_offsets[e + 1];
    if (row0 >= row_end) return;
    int rows = min(128, row_end - row0);

    extern __shared__ char dsm[];
    __shared__ int sTok[128];

    int tid = threadIdx.x;
    if (tid < 128) sTok[tid] = g_tok[row0 + ((tid < rows) ? tid : 0)];
    __syncthreads();

    uint32_t smem0 = smem_u32(dsm);
    const float* w1e = w1r + (size_t)e * DIM * FF;
    const float* w3e = w3r + (size_t)e * DIM * FF;
    int ncol0 = nt * 128;

    int warp = tid >> 5, lane = tid & 31;
    int wm = warp & 3, wn = warp >> 2;
    int mrow = wm * 32, ncol = wn * 32;
    int grp = lane >> 2, tig = lane & 3;
    int lm = lane >> 3, lr = lane & 7;
    uint32_t aOff = (uint32_t)(((lm & 1) * 8 + lr) * 144 + (lm >> 1) * 16);

    float accG[2][4][4], accV[2][4][4];
#pragma unroll
    for (int mi = 0; mi < 2; mi++)
#pragma unroll
        for (int ni = 0; ni < 4; ni++)
#pragma unroll
            for (int q = 0; q < 4; q++) { accG[mi][ni][q] = 0.f; accV[mi][ni][q] = 0.f; }

    fill1(smem0 + 0 * STG1, 0, ncol0, w1e, w3e, sTok, tid); CP_COMMIT();
    fill1(smem0 + 1 * STG1, 1, ncol0, w1e, w3e, sTok, tid); CP_COMMIT();

    const int KT = DIM / 32;   // 32
    for (int kt = 0; kt < KT; kt++) {
        CP_WAIT(1);
        __syncthreads();
        if (kt + 2 < KT)
            fill1(smem0 + ((kt + 2) % 3) * STG1, kt + 2, ncol0, w1e, w3e, sTok, tid);
        CP_COMMIT();

        uint32_t stOff = (uint32_t)((kt % 3) * STG1);
        const uint32_t* sB1 = (const uint32_t*)(dsm + stOff + A_BYTES);
        const uint32_t* sB3 = (const uint32_t*)(dsm + stOff + A_BYTES + B_BYTES);
        uint32_t aBase = smem0 + stOff + mrow * 144 + aOff;
#pragma unroll
        for (int kk = 0; kk < 32; kk += 8) {
            uint32_t a[2][4];
            ldsm_x4(a[0], aBase + kk * 4);
            ldsm_x4(a[1], aBase + 16 * 144 + kk * 4);
#pragma unroll
            for (int ni = 0; ni < 4; ni++) {
                int kb = (kk + tig) * SB_W + ncol + ni * 8 + grp;
                uint32_t b10 = sB1[kb], b11 = sB1[kb + 4 * SB_W];
                uint32_t b30 = sB3[kb], b31 = sB3[kb + 4 * SB_W];
#pragma unroll
                for (int mi = 0; mi < 2; mi++) {
                    mma_tf32(accG[mi][ni], a[mi], b10, b11);
                    mma_tf32(accV[mi][ni], a[mi], b30, b31);
                }
            }
        }
    }

    // epilogue: SwiGLU, round to tf32, store to g_H
#pragma unroll
    for (int mi = 0; mi < 2; mi++) {
#pragma unroll
        for (int ni = 0; ni < 4; ni++) {
            int r = mrow + mi * 16 + grp;
            int c = ncol + ni * 8 + tig * 2;
            size_t gc = (size_t)ncol0 + c;
            const float* g = accG[mi][ni];
            const float* v = accV[mi][ni];
            if (r < rows) {
                float h0 = silu_f(g[0]) * v[0];
                float h1 = silu_f(g[1]) * v[1];
                *(float2*)&g_H[(size_t)(row0 + r) * FF + gc] =
                    make_float2(__uint_as_float(f2tf32(h0)), __uint_as_float(f2tf32(h1)));
            }
            int r2 = r + 8;
            if (r2 < rows) {
                float h2 = silu_f(g[2]) * v[2];
                float h3 = silu_f(g[3]) * v[3];
                *(float2*)&g_H[(size_t)(row0 + r2) * FF + gc] =
                    make_float2(__uint_as_float(f2tf32(h2)), __uint_as_float(f2tf32(h3)));
            }
        }
    }
}

// ---------------- launch #7: GEMM2 g_H @ w2 -> g_R ----------------
// 256 threads, tile 128M x 128N, warps 4m x 2n, warp tile 32x64.
__device__ __forceinline__ void fill2(uint32_t sb, int kc, int ncol0,
                                      const float* __restrict__ w2e,
                                      int row0, int rows, int tid) {
    int k0 = kc * 32;
#pragma unroll
    for (int i = 0; i < 4; i++) {
        int c = tid + i * 256;
        int r = c >> 3, c4 = c & 7;
        int rsrc = row0 + ((r < rows) ? r : 0);
        const float* src = g_H + (size_t)rsrc * FF + k0 + c4 * 4;
        CP_ASYNC16(sb + r * 144 + c4 * 16, src);
    }
#pragma unroll
    for (int i = 0; i < 4; i++) {
        int c = tid + i * 256;
        int kr = c >> 5, n4 = c & 31;
        const float* src = w2e + (size_t)(k0 + kr) * DIM + ncol0 + n4 * 4;
        CP_ASYNC16(sb + A_BYTES + kr * 544 + n4 * 16, src);
    }
}

__global__ __launch_bounds__(256, 2)
void moe_gemm2(const float* __restrict__ w2r) {
    int bid = blockIdx.x;
    int nt = bid & 7, mt = (bid >> 3) & 63, e = bid >> 9;
    int row0 = g_offsets[e] + mt * 128;
    int row_end = g_offsets[e + 1];
    if (row0 >= row_end) return;
    int rows = min(128, row_end - row0);

    extern __shared__ char dsm[];
    int tid = threadIdx.x;
    uint32_t smem0 = smem_u32(dsm);
    const float* w2e = w2r + (size_t)e * FF * DIM;
    int ncol0 = nt * 128;

    int warp = tid >> 5, lane = tid & 31;
    int wm = warp & 3, wn = warp >> 2;
    int mrow = wm * 32, ncol = wn * 64;
    int grp = lane >> 2, tig = lane & 3;
    int lm = lane >> 3, lr = lane & 7;
    uint32_t aOff = (uint32_t)(((lm & 1) * 8 + lr) * 144 + (lm >> 1) * 16);

    float accC[2][8][4];
#pragma unroll
    for (int mi = 0; mi < 2; mi++)
#pragma unroll
        for (int ni = 0; ni < 8; ni++)
#pragma unroll
            for (int q = 0; q < 4; q++) accC[mi][ni][q] = 0.f;

    fill2(smem0 + 0 * STG2, 0, ncol0, w2e, row0, rows, tid); CP_COMMIT();
    fill2(smem0 + 1 * STG2, 1, ncol0, w2e, row0, rows, tid); CP_COMMIT();

    const int KT = FF / 32;   // 128
    for (int kt = 0; kt < KT; kt++) {
        CP_WAIT(1);
        __syncthreads();
        if (kt + 2 < KT)
            fill2(smem0 + ((kt + 2) % 3) * STG2, kt + 2, ncol0, w2e, row0, rows, tid);
        CP_COMMIT();

        uint32_t stOff = (uint32_t)((kt % 3) * STG2);
        const uint32_t* sB = (const uint32_t*)(dsm + stOff + A_BYTES);
        uint32_t aBase = smem0 + stOff + mrow * 144 + aOff;
#pragma unroll
        for (int kk = 0; kk < 32; kk += 8) {
            uint32_t a[2][4];
            ldsm_x4(a[0], aBase + kk * 4);
            ldsm_x4(a[1], aBase + 16 * 144 + kk * 4);
#pragma unroll
            for (int ni = 0; ni < 8; ni++) {
                int kb = (kk + tig) * SB_W + ncol + ni * 8 + grp;
                uint32_t b0 = sB[kb], b1 = sB[kb + 4 * SB_W];
#pragma unroll
                for (int mi = 0; mi < 2; mi++)
                    mma_tf32(accC[mi][ni], a[mi], b0, b1);
            }
        }
    }

    // epilogue: raw fp32 per-slot rows
#pragma unroll
    for (int mi = 0; mi < 2; mi++) {
#pragma unroll
        for (int ni = 0; ni < 8; ni++) {
            int r = mrow + mi * 16 + grp;
            int c = ncol + ni * 8 + tig * 2;
            size_t gc = (size_t)ncol0 + c;
            const float* a = accC[mi][ni];
            if (r < rows)
                *(float2*)&g_R[(size_t)(row0 + r) * DIM + gc] = make_float2(a[0], a[1]);
            int r2 = r + 8;
            if (r2 < rows)
                *(float2*)&g_R[(size_t)(row0 + r2) * DIM + gc] = make_float2(a[2], a[3]);
        }
    }
}

// ---------------- launch #8: combine out[t] = w0*R[s0] + w1*R[s1] ----------------
__global__ void moe_combine_kernel(float4* __restrict__ out4) {
    const int n = T_TOK * (DIM / 4);
    int i = blockIdx.x * blockDim.x + threadIdx.x;
    if (i >= n) return;
    int t = i >> 8;
    int c = i & 255;
    int s0 = g_slot[t * 2 + 0], s1 = g_slot[t * 2 + 1];
    float w0 = g_tok_w[t * 2 + 0], w1 = g_tok_w[t * 2 + 1];
    const float4* R4 = (const float4*)g_R;
    float4 a = R4[(size_t)s0 * 256 + c];
    float4 b = R4[(size_t)s1 * 256 + c];
    float4 o;
    o.x = w0 * a.x + w1 * b.x;
    o.y = w0 * a.y + w1 * b.y;
    o.z = w0 * a.z + w1 * b.z;
    o.w = w0 * a.w + w1 * b.w;
    out4[i] = o;
}

// ---------------- launch ----------------
extern "C" void kernel_launch(void* const* d_in, const int* in_sizes, int n_in,
                              void* d_out, int out_size) {
    (void)in_sizes; (void)n_in; (void)out_size;
    const float* x  = (const float*)d_in[0];
    const float* gw = (const float*)d_in[1];
    const float* w1 = (const float*)d_in[2];
    const float* w3 = (const float*)d_in[3];
    const float* w2 = (const float*)d_in[4];
    float* out = (float*)d_out;

    float* d_xr;  cudaGetSymbolAddress((void**)&d_xr,  g_xr);
    float* d_w1r; cudaGetSymbolAddress((void**)&d_w1r, g_w1r);
    float* d_w3r; cudaGetSymbolAddress((void**)&d_w3r, g_w3r);
    float* d_w2r; cudaGetSymbolAddress((void**)&d_w2r, g_w2r);

    const int DYN1 = 3 * STG1;   // 159744
    const int DYN2 = 3 * STG2;   // 107520
    cudaFuncSetAttribute(moe_gemm1, cudaFuncAttributeMaxDynamicSharedMemorySize, DYN1);
    cudaFuncSetAttribute(moe_gemm2, cudaFuncAttributeMaxDynamicSharedMemorySize, DYN2);

    int nw = NE * DIM * FF / 4;
    int nx = T_TOK * DIM / 4;
    // #1 weights round (one launch, gridDim.y=3)
    dim3 gw3((nw + 255) / 256, 3);
    moe_round_w<<<gw3, 256>>>((const float4*)w1, (float4*)d_w1r,
                              (const float4*)w3, (float4*)d_w3r,
                              (const float4*)w2, (float4*)d_w2r, nw);
    // #2 x round
    moe_round_x<<<(nx + 255) / 256, 256>>>((const float4*)x, (float4*)d_xr, nx);
    // #3 gate, #4 offsets, #5 scatter
    moe_gate_kernel<<<T_TOK / 8, 256>>>(x, gw);
    moe_offset_kernel<<<1, 256>>>();
    moe_scatter_kernel<<<T_TOK / 256, 256>>>();
    // #6 GEMM1: e(8) x nt(32) x mt(64), mt fastest (concurrent blocks share B slab)
    moe_gemm1<<<8 * 32 * 64, 512, DYN1>>>(d_w1r, d_w3r);
    // #7 GEMM2: e(8) x mt(64) x nt(8), nt fastest (concurrent blocks share H slab)
    moe_gemm2<<<8 * 64 * 8, 256, DYN2>>>(d_w2r);
    // #8 combine
    moe_combine_kernel<<<(T_TOK * DIM / 4 + 255) / 256, 256>>>((float4*)out);
}